// round 2
// baseline (speedup 1.0000x reference)
#include <cuda_runtime.h>
#include <math.h>

#define B_   8
#define T_   2048
#define CH_  48
#define NH_  36
#define NG_  3
#define H_   12
#define W_   18
#define L_   512
#define R_   4
#define NW_  9
#define TT_  16   // t-tile for lats kernel

// output element counts
#define LATS_ELEMS (8ull*2048ull*18ull*512ull)          // 150,994,944
#define N0_ELEMS   (8ull*2048ull*16ull)
#define N1_ELEMS   (8ull*2048ull*64ull)
#define N2_ELEMS   (8ull*2048ull*256ull)
#define N3_ELEMS   (8ull*2048ull*1024ull)

// scratch (no allocations allowed -> device globals)
__device__ float g_means[B_ * CH_];           // per-batch channel means
__device__ float g_w[B_ * 4 * NW_];           // gaussian weights per (b, noise)
__device__ float g_musm[4 * B_ * T_];         // smoothed mu per (noise, b, t)

// ---------------- f32x2 helpers ----------------
__device__ __forceinline__ unsigned long long pack2(float v) {
    unsigned long long r;
    asm("mov.b64 %0, {%1, %1};" : "=l"(r) : "f"(v));
    return r;
}
__device__ __forceinline__ unsigned long long packf2(float a, float b) {
    unsigned long long r;
    asm("mov.b64 %0, {%1, %2};" : "=l"(r) : "f"(a), "f"(b));
    return r;
}
__device__ __forceinline__ void unpack2(unsigned long long p, float& a, float& b) {
    asm("mov.b64 {%0, %1}, %2;" : "=f"(a), "=f"(b) : "l"(p));
}
__device__ __forceinline__ void fma2(unsigned long long& d,
                                     unsigned long long a,
                                     unsigned long long b) {
    asm("fma.rn.f32x2 %0, %1, %2, %0;" : "+l"(d) : "l"(a), "l"(b));
}

__device__ __forceinline__ int reflect_t(int t) {
    t = (t < 0) ? -t : t;
    return (t >= T_) ? (2 * T_ - 2 - t) : t;
}

// ---------------- kernel 1: per-batch channel means ----------------
__global__ void k_means(const float* __restrict__ x) {
    int b = blockIdx.x / CH_;
    int c = blockIdx.x % CH_;
    float s = 0.f;
    for (int t = threadIdx.x; t < T_; t += 256)
        s += x[(b * T_ + t) * CH_ + c];
    __shared__ float sh[256];
    sh[threadIdx.x] = s;
    __syncthreads();
    for (int o = 128; o > 0; o >>= 1) {
        if (threadIdx.x < o) sh[threadIdx.x] += sh[threadIdx.x + o];
        __syncthreads();
    }
    if (threadIdx.x == 0)
        g_means[blockIdx.x] = sh[0] * (1.0f / (float)T_);
}

// ---------------- kernel 2: gaussian weights ----------------
__global__ void k_weights() {
    if (threadIdx.x >= B_ * 4) return;
    int b = threadIdx.x / 4;
    int i = threadIdx.x % 4;
    float sig = fmaxf(g_means[b * CH_ + NH_ + 3 * i + 2], 0.001f);
    float inv = -0.5f / (sig * sig);
    float ws[NW_];
    float sum = 0.f;
#pragma unroll
    for (int j = 0; j < NW_; j++) {
        float k = (float)(j - R_);
        ws[j] = expf(k * k * inv);
        sum += ws[j];
    }
    float rs = 1.0f / sum;
#pragma unroll
    for (int j = 0; j < NW_; j++)
        g_w[(b * 4 + i) * NW_ + j] = ws[j] * rs;
}

// ---------------- kernel 3: smoothed mu per (noise, b, t) ----------------
__global__ void k_musm(const float* __restrict__ x) {
    int t = blockIdx.x * 256 + threadIdx.x;   // gridDim.x = T_/256
    int b = blockIdx.y;
    int i = blockIdx.z;
    float acc = 0.f;
#pragma unroll
    for (int j = 0; j < NW_; j++) {
        int tj = reflect_t(t + j - R_);
        acc += g_w[(b * 4 + i) * NW_ + j] * x[(b * T_ + tj) * CH_ + NH_ + 3 * i];
    }
    g_musm[(i * B_ + b) * T_ + t] = acc;
}

// ---------------- kernel 4: lats (fused einsum + mean-subtraction) ----------------
// out[b,t,w,l] = sum_h (env[b,t,hg] - env_mean[b,hg]) * table[hg, w, l],
//   hg = (w/6)*12 + h
__global__ void __launch_bounds__(256) k_lats(const float* __restrict__ x,
                                              const float* __restrict__ table,
                                              float* __restrict__ out) {
    int b = blockIdx.y;
    int t0 = blockIdx.x * TT_;

    __shared__ unsigned long long s_env[TT_ * NH_];
    for (int idx = threadIdx.x; idx < TT_ * NH_; idx += 256) {
        int t = idx / NH_;
        int c = idx % NH_;
        float v = x[(b * T_ + t0 + t) * CH_ + c] - g_means[b * CH_ + c];
        s_env[idx] = pack2(v);
    }
    __syncthreads();

    const float4* tab4 = (const float4*)table;
    float4* out4 = (float4*)out;
    size_t out_base = (size_t)(b * T_ + t0) * (W_ * L_ / 4);

#pragma unroll 1
    for (int k = 0; k < 9; k++) {
        int cidx = threadIdx.x + k * 256;     // 0..2303 float4 columns
        int w = cidx >> 7;                    // 0..17
        int g = w / 6;
        int lq = cidx & 127;                  // float4 index within the 512-l row

        // load the 12-h table column into registers as f32x2 pairs
        unsigned long long tl[H_], th[H_];
        int tbase = (g * H_ * W_ + w) * (L_ / 4) + lq;
#pragma unroll
        for (int h = 0; h < H_; h++) {
            float4 tv = tab4[tbase + h * (W_ * L_ / 4)];
            tl[h] = packf2(tv.x, tv.y);
            th[h] = packf2(tv.z, tv.w);
        }

        size_t obase = out_base + (size_t)w * (L_ / 4) + lq;
#pragma unroll
        for (int t = 0; t < TT_; t++) {
            unsigned long long a0 = 0ull, a1 = 0ull;
            const unsigned long long* ep = &s_env[t * NH_ + g * H_];
#pragma unroll
            for (int h = 0; h < H_; h++) {
                unsigned long long e = ep[h];
                fma2(a0, e, tl[h]);
                fma2(a1, e, th[h]);
            }
            float4 r;
            unpack2(a0, r.x, r.y);
            unpack2(a1, r.z, r.w);
            out4[obase + (size_t)t * (W_ * L_ / 4)] = r;
        }
    }
}

// ---------------- kernel 5: noise conv, t-run of 8 per thread ----------------
__global__ void __launch_bounds__(256) k_noise(const float* __restrict__ x,
                                               const float* __restrict__ eps,
                                               float* __restrict__ out,
                                               int i, int nf4) {
    int idx = blockIdx.x * 256 + threadIdx.x;
    int total = B_ * (T_ / 8) * nf4;
    if (idx >= total) return;
    int c = idx % nf4;
    int r = (idx / nf4) % (T_ / 8);
    int b = idx / (nf4 * (T_ / 8));
    int t0 = r * 8;

    float w[NW_];
#pragma unroll
    for (int j = 0; j < NW_; j++) w[j] = g_w[(b * 4 + i) * NW_ + j];

    int sigch = NH_ + 3 * i + 1;
    float s[16];
    float4 e[16];
    const float4* ep = (const float4*)eps;
#pragma unroll
    for (int k = 0; k < 16; k++) {
        int tt = t0 - R_ + k;
        tt = (tt < 0) ? -tt : ((tt >= T_) ? (2 * T_ - 2 - tt) : tt);
        s[k] = x[(b * T_ + tt) * CH_ + sigch];
        e[k] = ep[(size_t)(b * T_ + tt) * nf4 + c];
    }

    const float* mus = &g_musm[(i * B_ + b) * T_ + t0];
    float4* op = (float4*)out + (size_t)(b * T_ + t0) * nf4 + c;
#pragma unroll
    for (int u = 0; u < 8; u++) {
        float m = mus[u];
        float4 a = make_float4(m, m, m, m);
#pragma unroll
        for (int j = 0; j < NW_; j++) {
            float cf = w[j] * s[u + j];
            a.x = fmaf(cf, e[u + j].x, a.x);
            a.y = fmaf(cf, e[u + j].y, a.y);
            a.z = fmaf(cf, e[u + j].z, a.z);
            a.w = fmaf(cf, e[u + j].w, a.w);
        }
        op[(size_t)u * nf4] = a;
    }
}

extern "C" void kernel_launch(void* const* d_in, const int* in_sizes, int n_in,
                              void* d_out, int out_size) {
    const float* x     = (const float*)d_in[0];
    const float* table = (const float*)d_in[1];
    const float* eps0  = (const float*)d_in[2];
    const float* eps1  = (const float*)d_in[3];
    const float* eps2  = (const float*)d_in[4];
    const float* eps3  = (const float*)d_in[5];
    float* out = (float*)d_out;

    // stage 0: stats
    k_means<<<B_ * CH_, 256>>>(x);
    k_weights<<<1, 32>>>();
    k_musm<<<dim3(T_ / 256, B_, 4), 256>>>(x);

    // stage 1: lats
    k_lats<<<dim3(T_ / TT_, B_), 256>>>(x, table, out);

    // stage 2: noises (appended after lats in output buffer)
    size_t off = LATS_ELEMS;
    const float* epss[4] = {eps0, eps1, eps2, eps3};
    size_t nelems[4] = {N0_ELEMS, N1_ELEMS, N2_ELEMS, N3_ELEMS};
    for (int i = 0; i < 4; i++) {
        int s2 = (4 << i) * (4 << i);
        int nf4 = s2 / 4;
        int total = B_ * (T_ / 8) * nf4;
        int blocks = (total + 255) / 256;
        k_noise<<<blocks, 256>>>(x, epss[i], out + off, i, nf4);
        off += nelems[i];
    }
}

// round 3
// speedup vs baseline: 1.1606x; 1.1606x over previous
#include <cuda_runtime.h>
#include <math.h>

#define B_   8
#define T_   2048
#define CH_  48
#define NH_  36
#define H_   12
#define W_   18
#define L_   512
#define R_   4
#define NW_  9
#define TT_  16

#define LATS_ELEMS (8ull*2048ull*18ull*512ull)
#define N0_ELEMS   (8ull*2048ull*16ull)
#define N1_ELEMS   (8ull*2048ull*64ull)
#define N2_ELEMS   (8ull*2048ull*256ull)
#define N3_ELEMS   (8ull*2048ull*1024ull)

// noise blocks (256 threads each, t-run of 8 per thread):
// i: nf4 = 4,16,64,256 ; threads = 8*256*nf4 = 8192,32768,131072,524288
// blocks = 32,128,512,2048  (cumulative 32,160,672,2720)
#define NBLK0 32
#define NBLK1 128
#define NBLK2 512
#define NBLK3 2048
#define NOISE_BLOCKS (NBLK0+NBLK1+NBLK2+NBLK3)   // 2720
#define LATS_BLOCKS  ((T_/TT_)*B_)               // 8192

__device__ float g_means[B_ * CH_];
__device__ float g_w[B_ * 4 * NW_];

// ---------------- f32x2 helpers ----------------
__device__ __forceinline__ unsigned long long pack2(float v) {
    unsigned long long r;
    asm("mov.b64 %0, {%1, %1};" : "=l"(r) : "f"(v));
    return r;
}
__device__ __forceinline__ unsigned long long packf2(float a, float b) {
    unsigned long long r;
    asm("mov.b64 %0, {%1, %2};" : "=l"(r) : "f"(a), "f"(b));
    return r;
}
__device__ __forceinline__ void unpack2(unsigned long long p, float& a, float& b) {
    asm("mov.b64 {%0, %1}, %2;" : "=f"(a), "=f"(b) : "l"(p));
}
__device__ __forceinline__ void fma2(unsigned long long& d,
                                     unsigned long long a,
                                     unsigned long long b) {
    asm("fma.rn.f32x2 %0, %1, %2, %0;" : "+l"(d) : "l"(a), "l"(b));
}

__device__ __forceinline__ int reflect_t(int t) {
    t = (t < 0) ? -t : t;
    return (t >= T_) ? (2 * T_ - 2 - t) : t;
}

// ---------------- stats: per-batch channel means + gaussian weights ----------------
__global__ void k_stats(const float* __restrict__ x) {
    int b = blockIdx.x / CH_;
    int c = blockIdx.x % CH_;
    float s = 0.f;
    for (int t = threadIdx.x; t < T_; t += 256)
        s += x[(b * T_ + t) * CH_ + c];
    __shared__ float sh[256];
    sh[threadIdx.x] = s;
    __syncthreads();
    for (int o = 128; o > 0; o >>= 1) {
        if (threadIdx.x < o) sh[threadIdx.x] += sh[threadIdx.x + o];
        __syncthreads();
    }
    if (threadIdx.x == 0) {
        float mean = sh[0] * (1.0f / (float)T_);
        g_means[blockIdx.x] = mean;
        // if this is a smooth channel, also emit the gaussian weights
        int cc = c - NH_;
        if (cc >= 0 && (cc % 3) == 2) {
            int i = cc / 3;
            float sig = fmaxf(mean, 0.001f);
            float inv = -0.5f / (sig * sig);
            float ws[NW_];
            float sum = 0.f;
#pragma unroll
            for (int j = 0; j < NW_; j++) {
                float k = (float)(j - R_);
                ws[j] = expf(k * k * inv);
                sum += ws[j];
            }
            float rs = 1.0f / sum;
#pragma unroll
            for (int j = 0; j < NW_; j++)
                g_w[(b * 4 + i) * NW_ + j] = ws[j] * rs;
        }
    }
}

// ---------------- noise path (device func), rolling window ----------------
__device__ __forceinline__ void noise_path(const float* __restrict__ x,
                                           const float* __restrict__ eps,
                                           float* __restrict__ out,
                                           int i, int nf4, int nb) {
    int idx = nb * 256 + threadIdx.x;
    int c = idx % nf4;
    int r = (idx / nf4) % (T_ / 8);
    int b = idx / (nf4 * (T_ / 8));
    int t0 = r * 8;

    float w[NW_];
#pragma unroll
    for (int j = 0; j < NW_; j++) w[j] = g_w[(b * 4 + i) * NW_ + j];

    int much  = NH_ + 3 * i;
    int sigch = much + 1;

    const float4* ep = (const float4*)eps;
    float4* op = (float4*)out + (size_t)(b * T_ + t0) * nf4 + c;

    // rolling 9-deep window over tt = t0-4 .. t0+4, extended per-u
    float4 e[NW_];
    float  s[NW_], m[NW_];
#pragma unroll
    for (int k = 0; k < NW_; k++) {
        int tt = reflect_t(t0 - R_ + k);
        const float* xr = &x[(b * T_ + tt) * CH_];
        m[k] = xr[much];
        s[k] = xr[sigch];
        e[k] = ep[(size_t)(b * T_ + tt) * nf4 + c];
    }

#pragma unroll
    for (int u = 0; u < 8; u++) {
        float mu = 0.f;
        float4 a = make_float4(0.f, 0.f, 0.f, 0.f);
#pragma unroll
        for (int j = 0; j < NW_; j++) {
            int slot = (u + j) % NW_;
            mu += w[j] * m[slot];
            float cf = w[j] * s[slot];
            a.x = fmaf(cf, e[slot].x, a.x);
            a.y = fmaf(cf, e[slot].y, a.y);
            a.z = fmaf(cf, e[slot].z, a.z);
            a.w = fmaf(cf, e[slot].w, a.w);
        }
        a.x += mu; a.y += mu; a.z += mu; a.w += mu;
        op[(size_t)u * nf4] = a;
        // slide window: replace slot u%9 with tt = t0 + 5 + u
        if (u < 7) {
            int tt = reflect_t(t0 + R_ + 1 + u);
            int slot = u % NW_;
            const float* xr = &x[(b * T_ + tt) * CH_];
            m[slot] = xr[much];
            s[slot] = xr[sigch];
            e[slot] = ep[(size_t)(b * T_ + tt) * nf4 + c];
        }
    }
}

// ---------------- lats path (device func) ----------------
__device__ __forceinline__ void lats_path(const float* __restrict__ x,
                                          const float* __restrict__ table,
                                          float* __restrict__ out,
                                          int lb) {
    int b  = lb / (T_ / TT_);
    int t0 = (lb % (T_ / TT_)) * TT_;

    __shared__ unsigned long long s_env[TT_ * NH_];
    for (int idx = threadIdx.x; idx < TT_ * NH_; idx += 256) {
        int t = idx / NH_;
        int c = idx % NH_;
        float v = x[(b * T_ + t0 + t) * CH_ + c] - g_means[b * CH_ + c];
        s_env[idx] = pack2(v);
    }
    __syncthreads();

    const float4* tab4 = (const float4*)table;
    float4* out4 = (float4*)out;
    size_t out_base = (size_t)(b * T_ + t0) * (W_ * L_ / 4);

#pragma unroll 1
    for (int k = 0; k < 9; k++) {
        int cidx = threadIdx.x + k * 256;
        int w = cidx >> 7;
        int g = w / 6;
        int lq = cidx & 127;

        unsigned long long tl[H_], th[H_];
        int tbase = (g * H_ * W_ + w) * (L_ / 4) + lq;
#pragma unroll
        for (int h = 0; h < H_; h++) {
            float4 tv = tab4[tbase + h * (W_ * L_ / 4)];
            tl[h] = packf2(tv.x, tv.y);
            th[h] = packf2(tv.z, tv.w);
        }

        size_t obase = out_base + (size_t)w * (L_ / 4) + lq;
#pragma unroll
        for (int t = 0; t < TT_; t++) {
            unsigned long long a0 = 0ull, a1 = 0ull;
            const unsigned long long* ep2 = &s_env[t * NH_ + g * H_];
#pragma unroll
            for (int h = 0; h < H_; h++) {
                unsigned long long e = ep2[h];
                fma2(a0, e, tl[h]);
                fma2(a1, e, th[h]);
            }
            float4 rr;
            unpack2(a0, rr.x, rr.y);
            unpack2(a1, rr.z, rr.w);
            out4[obase + (size_t)t * (W_ * L_ / 4)] = rr;
        }
    }
}

// ---------------- über-kernel ----------------
__global__ void __launch_bounds__(256) k_uber(const float* __restrict__ x,
                                              const float* __restrict__ table,
                                              const float* __restrict__ eps0,
                                              const float* __restrict__ eps1,
                                              const float* __restrict__ eps2,
                                              const float* __restrict__ eps3,
                                              float* __restrict__ out) {
    int bid = blockIdx.x;
    if (bid < NOISE_BLOCKS) {
        int nb = bid;
        if (nb < NBLK0) {
            noise_path(x, eps0, out + LATS_ELEMS, 0, 4, nb);
        } else if (nb < NBLK0 + NBLK1) {
            noise_path(x, eps1, out + LATS_ELEMS + N0_ELEMS, 1, 16, nb - NBLK0);
        } else if (nb < NBLK0 + NBLK1 + NBLK2) {
            noise_path(x, eps2, out + LATS_ELEMS + N0_ELEMS + N1_ELEMS, 2, 64,
                       nb - (NBLK0 + NBLK1));
        } else {
            noise_path(x, eps3, out + LATS_ELEMS + N0_ELEMS + N1_ELEMS + N2_ELEMS, 3, 256,
                       nb - (NBLK0 + NBLK1 + NBLK2));
        }
    } else {
        lats_path(x, table, out, bid - NOISE_BLOCKS);
    }
}

extern "C" void kernel_launch(void* const* d_in, const int* in_sizes, int n_in,
                              void* d_out, int out_size) {
    const float* x     = (const float*)d_in[0];
    const float* table = (const float*)d_in[1];
    const float* eps0  = (const float*)d_in[2];
    const float* eps1  = (const float*)d_in[3];
    const float* eps2  = (const float*)d_in[4];
    const float* eps3  = (const float*)d_in[5];
    float* out = (float*)d_out;

    k_stats<<<B_ * CH_, 256>>>(x);
    k_uber<<<NOISE_BLOCKS + LATS_BLOCKS, 256>>>(x, table, eps0, eps1, eps2, eps3, out);
}

// round 4
// speedup vs baseline: 1.2117x; 1.0440x over previous
#include <cuda_runtime.h>
#include <math.h>

#define B_   8
#define T_   2048
#define CH_  48
#define NH_  36
#define H_   12
#define W_   18
#define L_   512
#define R_   4
#define NW_  9
#define TT_  16

#define LATS_ELEMS (8ull*2048ull*18ull*512ull)
#define N0_ELEMS   (8ull*2048ull*16ull)
#define N1_ELEMS   (8ull*2048ull*64ull)
#define N2_ELEMS   (8ull*2048ull*256ull)
#define N3_ELEMS   (8ull*2048ull*1024ull)

#define NBLK0 32
#define NBLK1 128
#define NBLK2 512
#define NBLK3 2048
#define NOISE_BLOCKS (NBLK0+NBLK1+NBLK2+NBLK3)   // 2720
#define LATS_BLOCKS  ((T_/TT_)*B_)               // 8192

__device__ float g_means[B_ * CH_];
__device__ float g_w[B_ * 4 * NW_];

// ---------------- f32x2 helpers ----------------
__device__ __forceinline__ unsigned long long pack2(float v) {
    unsigned long long r;
    asm("mov.b64 %0, {%1, %1};" : "=l"(r) : "f"(v));
    return r;
}
__device__ __forceinline__ unsigned long long packf2(float a, float b) {
    unsigned long long r;
    asm("mov.b64 %0, {%1, %2};" : "=l"(r) : "f"(a), "f"(b));
    return r;
}
__device__ __forceinline__ void unpack2(unsigned long long p, float& a, float& b) {
    asm("mov.b64 {%0, %1}, %2;" : "=f"(a), "=f"(b) : "l"(p));
}
__device__ __forceinline__ void fma2(unsigned long long& d,
                                     unsigned long long a,
                                     unsigned long long b) {
    asm("fma.rn.f32x2 %0, %1, %2, %0;" : "+l"(d) : "l"(a), "l"(b));
}

__device__ __forceinline__ int reflect_t(int t) {
    t = (t < 0) ? -t : t;
    return (t >= T_) ? (2 * T_ - 2 - t) : t;
}

// ---------------- stats v2: coalesced per-batch channel means + weights ----------
// grid = 8 (one block per b), 384 threads.
// Thread layout: c4 = tid%12 (float4 column of the 48-ch row), r0 = tid/12 (0..31).
// 64 iterations of 32 rows: fully coalesced float4 reads.
__global__ void __launch_bounds__(384) k_stats(const float* __restrict__ x) {
    int b  = blockIdx.x;
    int c4 = threadIdx.x % 12;
    int r0 = threadIdx.x / 12;

    const float4* x4 = (const float4*)x;
    float4 acc = make_float4(0.f, 0.f, 0.f, 0.f);
#pragma unroll 4
    for (int it = 0; it < 64; it++) {
        int row = it * 32 + r0;
        float4 v = __ldcs(&x4[(size_t)(b * T_ + row) * 12 + c4]);
        acc.x += v.x; acc.y += v.y; acc.z += v.z; acc.w += v.w;
    }

    __shared__ float sh[32][CH_];
    sh[r0][c4 * 4 + 0] = acc.x;
    sh[r0][c4 * 4 + 1] = acc.y;
    sh[r0][c4 * 4 + 2] = acc.z;
    sh[r0][c4 * 4 + 3] = acc.w;
    __syncthreads();

    if (threadIdx.x < CH_) {
        int c = threadIdx.x;
        float s = 0.f;
#pragma unroll
        for (int r = 0; r < 32; r++) s += sh[r][c];
        float mean = s * (1.0f / (float)T_);
        g_means[b * CH_ + c] = mean;
        int cc = c - NH_;
        if (cc >= 0 && (cc % 3) == 2) {
            int i = cc / 3;
            float sig = fmaxf(mean, 0.001f);
            float inv = -0.5f / (sig * sig);
            float ws[NW_];
            float sum = 0.f;
#pragma unroll
            for (int j = 0; j < NW_; j++) {
                float k = (float)(j - R_);
                ws[j] = expf(k * k * inv);
                sum += ws[j];
            }
            float rs = 1.0f / sum;
#pragma unroll
            for (int j = 0; j < NW_; j++)
                g_w[(b * 4 + i) * NW_ + j] = ws[j] * rs;
        }
    }
}

// ---------------- noise path (device func), rolling window ----------------
__device__ __forceinline__ void noise_path(const float* __restrict__ x,
                                           const float* __restrict__ eps,
                                           float* __restrict__ out,
                                           int i, int nf4, int nb) {
    int idx = nb * 256 + threadIdx.x;
    int c = idx % nf4;
    int r = (idx / nf4) % (T_ / 8);
    int b = idx / (nf4 * (T_ / 8));
    int t0 = r * 8;

    float w[NW_];
#pragma unroll
    for (int j = 0; j < NW_; j++) w[j] = g_w[(b * 4 + i) * NW_ + j];

    int much  = NH_ + 3 * i;
    int sigch = much + 1;

    const float4* ep = (const float4*)eps;
    float4* op = (float4*)out + (size_t)(b * T_ + t0) * nf4 + c;

    float4 e[NW_];
    float  s[NW_], m[NW_];
#pragma unroll
    for (int k = 0; k < NW_; k++) {
        int tt = reflect_t(t0 - R_ + k);
        const float* xr = &x[(b * T_ + tt) * CH_];
        m[k] = xr[much];
        s[k] = xr[sigch];
        e[k] = __ldcs(&ep[(size_t)(b * T_ + tt) * nf4 + c]);
    }

#pragma unroll
    for (int u = 0; u < 8; u++) {
        float mu = 0.f;
        float4 a = make_float4(0.f, 0.f, 0.f, 0.f);
#pragma unroll
        for (int j = 0; j < NW_; j++) {
            int slot = (u + j) % NW_;
            mu += w[j] * m[slot];
            float cf = w[j] * s[slot];
            a.x = fmaf(cf, e[slot].x, a.x);
            a.y = fmaf(cf, e[slot].y, a.y);
            a.z = fmaf(cf, e[slot].z, a.z);
            a.w = fmaf(cf, e[slot].w, a.w);
        }
        a.x += mu; a.y += mu; a.z += mu; a.w += mu;
        __stcs(&op[(size_t)u * nf4], a);
        if (u < 7) {
            int tt = reflect_t(t0 + R_ + 1 + u);
            int slot = u % NW_;
            const float* xr = &x[(b * T_ + tt) * CH_];
            m[slot] = xr[much];
            s[slot] = xr[sigch];
            e[slot] = __ldcs(&ep[(size_t)(b * T_ + tt) * nf4 + c]);
        }
    }
}

// ---------------- lats path (device func) ----------------
__device__ __forceinline__ void lats_path(const float* __restrict__ x,
                                          const float* __restrict__ table,
                                          float* __restrict__ out,
                                          int lb) {
    int b  = lb / (T_ / TT_);
    int t0 = (lb % (T_ / TT_)) * TT_;

    __shared__ unsigned long long s_env[TT_ * NH_];
    for (int idx = threadIdx.x; idx < TT_ * NH_; idx += 256) {
        int t = idx / NH_;
        int c = idx % NH_;
        float v = x[(b * T_ + t0 + t) * CH_ + c] - g_means[b * CH_ + c];
        s_env[idx] = pack2(v);
    }
    __syncthreads();

    const float4* tab4 = (const float4*)table;
    float4* out4 = (float4*)out;
    size_t out_base = (size_t)(b * T_ + t0) * (W_ * L_ / 4);

#pragma unroll 1
    for (int k = 0; k < 9; k++) {
        int cidx = threadIdx.x + k * 256;
        int w = cidx >> 7;
        int g = w / 6;
        int lq = cidx & 127;

        unsigned long long tl[H_], th[H_];
        int tbase = (g * H_ * W_ + w) * (L_ / 4) + lq;
#pragma unroll
        for (int h = 0; h < H_; h++) {
            float4 tv = __ldg(&tab4[tbase + h * (W_ * L_ / 4)]);
            tl[h] = packf2(tv.x, tv.y);
            th[h] = packf2(tv.z, tv.w);
        }

        size_t obase = out_base + (size_t)w * (L_ / 4) + lq;
#pragma unroll
        for (int t = 0; t < TT_; t++) {
            unsigned long long a0 = 0ull, a1 = 0ull;
            const unsigned long long* ep2 = &s_env[t * NH_ + g * H_];
#pragma unroll
            for (int h = 0; h < H_; h++) {
                unsigned long long e = ep2[h];
                fma2(a0, e, tl[h]);
                fma2(a1, e, th[h]);
            }
            float4 rr;
            unpack2(a0, rr.x, rr.y);
            unpack2(a1, rr.z, rr.w);
            __stcs(&out4[obase + (size_t)t * (W_ * L_ / 4)], rr);
        }
    }
}

// ---------------- über-kernel ----------------
__global__ void __launch_bounds__(256, 3) k_uber(const float* __restrict__ x,
                                                 const float* __restrict__ table,
                                                 const float* __restrict__ eps0,
                                                 const float* __restrict__ eps1,
                                                 const float* __restrict__ eps2,
                                                 const float* __restrict__ eps3,
                                                 float* __restrict__ out) {
    int bid = blockIdx.x;
    if (bid < NOISE_BLOCKS) {
        int nb = bid;
        if (nb < NBLK0) {
            noise_path(x, eps0, out + LATS_ELEMS, 0, 4, nb);
        } else if (nb < NBLK0 + NBLK1) {
            noise_path(x, eps1, out + LATS_ELEMS + N0_ELEMS, 1, 16, nb - NBLK0);
        } else if (nb < NBLK0 + NBLK1 + NBLK2) {
            noise_path(x, eps2, out + LATS_ELEMS + N0_ELEMS + N1_ELEMS, 2, 64,
                       nb - (NBLK0 + NBLK1));
        } else {
            noise_path(x, eps3, out + LATS_ELEMS + N0_ELEMS + N1_ELEMS + N2_ELEMS, 3, 256,
                       nb - (NBLK0 + NBLK1 + NBLK2));
        }
    } else {
        lats_path(x, table, out, bid - NOISE_BLOCKS);
    }
}

extern "C" void kernel_launch(void* const* d_in, const int* in_sizes, int n_in,
                              void* d_out, int out_size) {
    const float* x     = (const float*)d_in[0];
    const float* table = (const float*)d_in[1];
    const float* eps0  = (const float*)d_in[2];
    const float* eps1  = (const float*)d_in[3];
    const float* eps2  = (const float*)d_in[4];
    const float* eps3  = (const float*)d_in[5];
    float* out = (float*)d_out;

    k_stats<<<B_, 384>>>(x);
    k_uber<<<NOISE_BLOCKS + LATS_BLOCKS, 256>>>(x, table, eps0, eps1, eps2, eps3, out);
}